// round 1
// baseline (speedup 1.0000x reference)
#include <cuda_runtime.h>
#include <math.h>

// Problem constants
#define BB   4
#define TT   2048
#define CC   768
#define NH   12
#define HSZ  64
#define C3   (3*CC)
#define MTOT (BB*TT)      // 8192

// Scratch (allocation-free: __device__ globals)
__device__ float g_qkv[(size_t)MTOT * C3];   // [B*T, 3C]
__device__ float g_y[(size_t)MTOT * CC];     // [B*T, C]  attention output (pre-proj)

// ---------------------------------------------------------------------------
// Tiled SGEMM: C[M,N] = A[M,K] @ B[K,N] + bias[N]
// BM=BN=128, BK=16, TM=TN=8, 256 threads. M,N,K multiples of tile sizes.
// ---------------------------------------------------------------------------
__global__ __launch_bounds__(256) void gemm_bias_kernel(
    const float* __restrict__ A, const float* __restrict__ Bm,
    const float* __restrict__ bias, float* __restrict__ C,
    int M, int N, int K)
{
    const int BM = 128, BN = 128, BK = 16;
    __shared__ float As[BK][BM];      // transposed A tile
    __shared__ float Bs[BK][BN];

    int tid = threadIdx.x;
    int tx  = tid & 15;               // 0..15 -> N
    int ty  = tid >> 4;               // 0..15 -> M
    int m0  = blockIdx.y * BM;
    int n0  = blockIdx.x * BN;

    float acc[8][8];
    #pragma unroll
    for (int i = 0; i < 8; i++)
        #pragma unroll
        for (int j = 0; j < 8; j++) acc[i][j] = 0.f;

    for (int k0 = 0; k0 < K; k0 += BK) {
        // Load A tile (BM x BK) -> As[k][m] (transposed). 512 float4, 2/thread.
        #pragma unroll
        for (int r = 0; r < 2; r++) {
            int idx = tid + r * 256;          // float4 index
            int row = idx >> 2;               // 4 float4 per row (BK/4)
            int kk4 = idx & 3;
            float4 v = *(const float4*)(A + (size_t)(m0 + row) * K + k0 + kk4 * 4);
            As[kk4*4+0][row] = v.x;
            As[kk4*4+1][row] = v.y;
            As[kk4*4+2][row] = v.z;
            As[kk4*4+3][row] = v.w;
        }
        // Load B tile (BK x BN). 512 float4, 2/thread, coalesced.
        #pragma unroll
        for (int r = 0; r < 2; r++) {
            int idx = tid + r * 256;
            int row = idx >> 5;               // 32 float4 per row (BN/4)
            int n4  = idx & 31;
            float4 v = *(const float4*)(Bm + (size_t)(k0 + row) * N + n0 + n4 * 4);
            *(float4*)&Bs[row][n4 * 4] = v;
        }
        __syncthreads();

        #pragma unroll
        for (int k = 0; k < BK; k++) {
            float a[8], b[8];
            *(float4*)&a[0] = *(const float4*)&As[k][ty * 8];
            *(float4*)&a[4] = *(const float4*)&As[k][ty * 8 + 4];
            *(float4*)&b[0] = *(const float4*)&Bs[k][tx * 8];
            *(float4*)&b[4] = *(const float4*)&Bs[k][tx * 8 + 4];
            #pragma unroll
            for (int i = 0; i < 8; i++)
                #pragma unroll
                for (int j = 0; j < 8; j++)
                    acc[i][j] += a[i] * b[j];
        }
        __syncthreads();
    }

    // Epilogue: add bias, store
    #pragma unroll
    for (int i = 0; i < 8; i++) {
        int row = m0 + ty * 8 + i;
        #pragma unroll
        for (int j4 = 0; j4 < 2; j4++) {
            int col = n0 + tx * 8 + j4 * 4;
            float4 bv = *(const float4*)(bias + col);
            float4 o;
            o.x = acc[i][j4*4+0] + bv.x;
            o.y = acc[i][j4*4+1] + bv.y;
            o.z = acc[i][j4*4+2] + bv.z;
            o.w = acc[i][j4*4+3] + bv.w;
            *(float4*)(C + (size_t)row * N + col) = o;
        }
    }
}

// ---------------------------------------------------------------------------
// Flash attention, causal. One CTA per (q-tile of 64 rows, head, batch).
// 256 threads as 16x16; each thread owns a 4x4 S tile and 4x4 O tile.
// Q,K stored d-major in smem (transposed); P reuses K's smem, stored [c][r].
// ---------------------------------------------------------------------------
__global__ __launch_bounds__(256) void attn_kernel(void)
{
    __shared__ float Qs[64][64];   // Qs[d][r]
    __shared__ float KPs[64][64];  // phase 1: K^T -> KPs[d][c]; phase 2: P -> KPs[c][r]
    __shared__ float Vs[64][64];   // Vs[c][d]

    const int qt = blockIdx.x;     // 0..31
    const int h  = blockIdx.y;     // 0..11
    const int b  = blockIdx.z;     // 0..3
    const int tid = threadIdx.x;
    const int tx = tid & 15;
    const int ty = tid >> 4;

    const float* qbase = g_qkv + (size_t)b * TT * C3 + h * HSZ;
    const float* kbase = qbase + CC;
    const float* vbase = qbase + 2 * CC;

    // Load Q tile transposed: Qs[d][r] = q[qt*64 + r][d]
    #pragma unroll
    for (int it = 0; it < 4; it++) {
        int idx = tid + it * 256;      // float4 index, 1024 total
        int r   = idx >> 4;            // 16 float4 per row
        int d4  = idx & 15;
        float4 v = *(const float4*)(qbase + (size_t)(qt * 64 + r) * C3 + d4 * 4);
        Qs[d4*4+0][r] = v.x;
        Qs[d4*4+1][r] = v.y;
        Qs[d4*4+2][r] = v.z;
        Qs[d4*4+3][r] = v.w;
    }

    float m_i[4], l_i[4], o[4][4];
    #pragma unroll
    for (int i = 0; i < 4; i++) {
        m_i[i] = -1e30f; l_i[i] = 0.f;
        #pragma unroll
        for (int j = 0; j < 4; j++) o[i][j] = 0.f;
    }

    const float scale = 0.125f;        // 1/sqrt(64)

    for (int kt = 0; kt <= qt; kt++) {
        __syncthreads();   // previous iteration's P@V readers done with KPs/Vs
        // Load K tile transposed and V tile
        #pragma unroll
        for (int it = 0; it < 4; it++) {
            int idx = tid + it * 256;
            int c   = idx >> 4;
            int d4  = idx & 15;
            float4 kv = *(const float4*)(kbase + (size_t)(kt * 64 + c) * C3 + d4 * 4);
            KPs[d4*4+0][c] = kv.x;
            KPs[d4*4+1][c] = kv.y;
            KPs[d4*4+2][c] = kv.z;
            KPs[d4*4+3][c] = kv.w;
            float4 vv = *(const float4*)(vbase + (size_t)(kt * 64 + c) * C3 + d4 * 4);
            *(float4*)&Vs[c][d4 * 4] = vv;
        }
        __syncthreads();

        // S = Q K^T (registers)
        float s[4][4];
        #pragma unroll
        for (int i = 0; i < 4; i++)
            #pragma unroll
            for (int j = 0; j < 4; j++) s[i][j] = 0.f;
        #pragma unroll 8
        for (int d = 0; d < 64; d++) {
            float4 q4 = *(const float4*)&Qs[d][ty * 4];
            float4 k4 = *(const float4*)&KPs[d][tx * 4];
            float qr[4] = {q4.x, q4.y, q4.z, q4.w};
            float kr[4] = {k4.x, k4.y, k4.z, k4.w};
            #pragma unroll
            for (int i = 0; i < 4; i++)
                #pragma unroll
                for (int j = 0; j < 4; j++)
                    s[i][j] += qr[i] * kr[j];
        }

        // scale + causal mask (only diagonal tile needs masking)
        if (kt == qt) {
            #pragma unroll
            for (int i = 0; i < 4; i++)
                #pragma unroll
                for (int j = 0; j < 4; j++) {
                    int rr = ty * 4 + i, cc = tx * 4 + j;
                    s[i][j] = (cc > rr) ? -1e30f : s[i][j] * scale;
                }
        } else {
            #pragma unroll
            for (int i = 0; i < 4; i++)
                #pragma unroll
                for (int j = 0; j < 4; j++) s[i][j] *= scale;
        }

        // Row max across 4 local cols + 16 lanes (half-warp butterflies)
        float mt[4];
        #pragma unroll
        for (int i = 0; i < 4; i++) {
            float m = fmaxf(fmaxf(s[i][0], s[i][1]), fmaxf(s[i][2], s[i][3]));
            #pragma unroll
            for (int sh = 1; sh < 16; sh <<= 1)
                m = fmaxf(m, __shfl_xor_sync(0xffffffffu, m, sh));
            mt[i] = m;
        }

        float alpha[4];
        #pragma unroll
        for (int i = 0; i < 4; i++) {
            float mn = fmaxf(m_i[i], mt[i]);
            alpha[i] = __expf(m_i[i] - mn);
            m_i[i] = mn;
        }

        // P = exp(S - m), row sums
        float rs[4];
        #pragma unroll
        for (int i = 0; i < 4; i++) {
            float r = 0.f;
            #pragma unroll
            for (int j = 0; j < 4; j++) {
                s[i][j] = __expf(s[i][j] - m_i[i]);
                r += s[i][j];
            }
            #pragma unroll
            for (int sh = 1; sh < 16; sh <<= 1)
                r += __shfl_xor_sync(0xffffffffu, r, sh);
            rs[i] = r;
        }
        #pragma unroll
        for (int i = 0; i < 4; i++) {
            l_i[i] = alpha[i] * l_i[i] + rs[i];
            #pragma unroll
            for (int j = 0; j < 4; j++) o[i][j] *= alpha[i];
        }

        __syncthreads();   // all threads done reading K from KPs
        // Write P transposed: KPs[c][r]
        #pragma unroll
        for (int i = 0; i < 4; i++)
            #pragma unroll
            for (int j = 0; j < 4; j++)
                KPs[tx * 4 + j][ty * 4 + i] = s[i][j];
        __syncthreads();

        // O += P @ V
        #pragma unroll 8
        for (int k = 0; k < 64; k++) {
            float4 p4 = *(const float4*)&KPs[k][ty * 4];
            float4 v4 = *(const float4*)&Vs[k][tx * 4];
            float pr[4] = {p4.x, p4.y, p4.z, p4.w};
            float vr[4] = {v4.x, v4.y, v4.z, v4.w};
            #pragma unroll
            for (int i = 0; i < 4; i++)
                #pragma unroll
                for (int j = 0; j < 4; j++)
                    o[i][j] += pr[i] * vr[j];
        }
    }

    // Normalize and store to g_y in [B, T, C] layout (C = h*64 + d)
    #pragma unroll
    for (int i = 0; i < 4; i++) {
        float inv = 1.f / l_i[i];
        int r = qt * 64 + ty * 4 + i;
        float4 ov;
        ov.x = o[i][0] * inv;
        ov.y = o[i][1] * inv;
        ov.z = o[i][2] * inv;
        ov.w = o[i][3] * inv;
        *(float4*)(g_y + (size_t)(b * TT + r) * CC + h * HSZ + tx * 4) = ov;
    }
}

// ---------------------------------------------------------------------------
extern "C" void kernel_launch(void* const* d_in, const int* in_sizes, int n_in,
                              void* d_out, int out_size)
{
    const float* x      = (const float*)d_in[0];
    const float* w_attn = (const float*)d_in[1];
    const float* b_attn = (const float*)d_in[2];
    const float* w_proj = (const float*)d_in[3];
    const float* b_proj = (const float*)d_in[4];
    float* out = (float*)d_out;

    float* qkv; float* y;
    cudaGetSymbolAddress((void**)&qkv, g_qkv);
    cudaGetSymbolAddress((void**)&y,   g_y);

    // 1) qkv = x @ w_attn + b_attn   [8192, 2304]
    {
        dim3 grid(C3 / 128, MTOT / 128);
        gemm_bias_kernel<<<grid, 256>>>(x, w_attn, b_attn, qkv, MTOT, C3, CC);
    }
    // 2) flash attention -> g_y [8192, 768]
    {
        dim3 grid(TT / 64, NH, BB);
        attn_kernel<<<grid, 256>>>();
    }
    // 3) out = y @ w_proj + b_proj   [8192, 768]
    {
        dim3 grid(CC / 128, MTOT / 128);
        gemm_bias_kernel<<<grid, 256>>>(y, w_proj, b_proj, out, MTOT, CC, CC);
    }
}

// round 3
// speedup vs baseline: 3.5461x; 3.5461x over previous
#include <cuda_runtime.h>
#include <cstdint>
#include <math.h>

// Problem constants
#define BB   4
#define TT   2048
#define CC   768
#define NH   12
#define HSZ  64
#define C3   (3*CC)
#define MTOT (BB*TT)      // 8192

// Scratch (allocation-free: __device__ globals)
__device__ float g_qkv[(size_t)MTOT * C3];   // [B*T, 3C]
__device__ float g_y[(size_t)MTOT * CC];     // [B*T, C]

// ---------------------------------------------------------------------------
// tf32 helpers (mma.sync m16n8k8 — generic sm_80+ path, no sm_103a features)
// ---------------------------------------------------------------------------
__device__ __forceinline__ float tf32f(float x) {
    uint32_t u;
    asm("cvt.rna.tf32.f32 %0, %1;" : "=r"(u) : "f"(x));
    return __uint_as_float(u);
}
__device__ __forceinline__ uint32_t tf32u(float x) {
    uint32_t u;
    asm("cvt.rna.tf32.f32 %0, %1;" : "=r"(u) : "f"(x));
    return u;
}
__device__ __forceinline__ void mma_tf32(float c[4], const uint32_t a[4],
                                         uint32_t b0, uint32_t b1) {
    asm volatile(
        "mma.sync.aligned.m16n8k8.row.col.f32.tf32.tf32.f32 "
        "{%0,%1,%2,%3}, {%4,%5,%6,%7}, {%8,%9}, {%0,%1,%2,%3};"
        : "+f"(c[0]), "+f"(c[1]), "+f"(c[2]), "+f"(c[3])
        : "r"(a[0]), "r"(a[1]), "r"(a[2]), "r"(a[3]), "r"(b0), "r"(b1));
}

// ===========================================================================
// Tensor-core GEMM: C[M,N] = A[M,K] @ B[K,N] + bias[N]
// CTA 128x128, BK=32, 8 warps (2x4) of 64x32. Double-buffered smem,
// register-staged global loads. M%128==0, N%128==0, K%32==0.
// ===========================================================================
#define GA_PITCH 36     // As lane addr ≡ 4g+t (mod 32): conflict-free frags
#define GB_PITCH 136    // Bs lane addr ≡ 8t+g (mod 32): conflict-free frags
#define GSMEM_FLOATS (2*128*GA_PITCH + 2*32*GB_PITCH)

__global__ __launch_bounds__(256) void gemm_tc_kernel(
    const float* __restrict__ A, const float* __restrict__ B,
    const float* __restrict__ bias, float* __restrict__ C,
    int M, int N, int K)
{
    extern __shared__ float sm[];
    float (*As)[128][GA_PITCH] = (float(*)[128][GA_PITCH])sm;
    float (*Bs)[32][GB_PITCH]  = (float(*)[32][GB_PITCH])(sm + 2*128*GA_PITCH);

    const int tid = threadIdx.x;
    const int wid = tid >> 5, lane = tid & 31;
    const int g = lane >> 2, t = lane & 3;
    const int wm = wid >> 2, wn = wid & 3;       // warp grid 2 x 4
    const int m0 = blockIdx.y * 128, n0 = blockIdx.x * 128;

    // loader mapping
    const int arow = tid >> 3, ak4 = tid & 7;        // +256 -> +32 rows
    const int brow = tid >> 5, bn4 = tid & 31;       // +256 -> +8 rows

    float4 stA[4], stB[4];
    auto ldg = [&](int k0) {
        #pragma unroll
        for (int r = 0; r < 4; r++)
            stA[r] = *(const float4*)(A + (size_t)(m0 + arow + r*32) * K + k0 + ak4*4);
        #pragma unroll
        for (int r = 0; r < 4; r++)
            stB[r] = *(const float4*)(B + (size_t)(k0 + brow + r*8) * N + n0 + bn4*4);
    };
    auto sts = [&](int s) {
        #pragma unroll
        for (int r = 0; r < 4; r++) {
            float4 c4;
            c4.x = tf32f(stA[r].x); c4.y = tf32f(stA[r].y);
            c4.z = tf32f(stA[r].z); c4.w = tf32f(stA[r].w);
            *(float4*)&As[s][arow + r*32][ak4*4] = c4;
        }
        #pragma unroll
        for (int r = 0; r < 4; r++) {
            float4 c4;
            c4.x = tf32f(stB[r].x); c4.y = tf32f(stB[r].y);
            c4.z = tf32f(stB[r].z); c4.w = tf32f(stB[r].w);
            *(float4*)&Bs[s][brow + r*8][bn4*4] = c4;
        }
    };

    float acc[4][4][4];
    #pragma unroll
    for (int mt = 0; mt < 4; mt++)
        #pragma unroll
        for (int nt = 0; nt < 4; nt++)
            #pragma unroll
            for (int j = 0; j < 4; j++) acc[mt][nt][j] = 0.f;

    ldg(0);
    sts(0);
    __syncthreads();

    const int nk = K >> 5;
    for (int i = 0; i < nk; i++) {
        const int s = i & 1;
        if (i + 1 < nk) ldg((i + 1) << 5);   // prefetch into regs

        #pragma unroll
        for (int ks = 0; ks < 4; ks++) {
            uint32_t af[4][4];
            #pragma unroll
            for (int mt = 0; mt < 4; mt++) {
                const int row = wm*64 + mt*16;
                af[mt][0] = __float_as_uint(As[s][row + g    ][ks*8 + t    ]);
                af[mt][1] = __float_as_uint(As[s][row + g + 8][ks*8 + t    ]);
                af[mt][2] = __float_as_uint(As[s][row + g    ][ks*8 + t + 4]);
                af[mt][3] = __float_as_uint(As[s][row + g + 8][ks*8 + t + 4]);
            }
            #pragma unroll
            for (int nt = 0; nt < 4; nt++) {
                uint32_t b0 = __float_as_uint(Bs[s][ks*8 + t    ][wn*32 + nt*8 + g]);
                uint32_t b1 = __float_as_uint(Bs[s][ks*8 + t + 4][wn*32 + nt*8 + g]);
                #pragma unroll
                for (int mt = 0; mt < 4; mt++)
                    mma_tf32(acc[mt][nt], af[mt], b0, b1);
            }
        }
        if (i + 1 < nk) {
            sts(s ^ 1);
            __syncthreads();
        }
    }

    // epilogue: bias + store (each 4-lane group covers one 32B sector)
    float2 bv[4];
    #pragma unroll
    for (int nt = 0; nt < 4; nt++)
        bv[nt] = *(const float2*)(bias + n0 + wn*32 + nt*8 + 2*t);
    #pragma unroll
    for (int mt = 0; mt < 4; mt++) {
        const int row = m0 + wm*64 + mt*16 + g;
        #pragma unroll
        for (int nt = 0; nt < 4; nt++) {
            const int col = n0 + wn*32 + nt*8 + 2*t;
            float2 o0 = { acc[mt][nt][0] + bv[nt].x, acc[mt][nt][1] + bv[nt].y };
            *(float2*)(C + (size_t)row * N + col) = o0;
            float2 o1 = { acc[mt][nt][2] + bv[nt].x, acc[mt][nt][3] + bv[nt].y };
            *(float2*)(C + (size_t)(row + 8) * N + col) = o1;
        }
    }
}

// ===========================================================================
// Flash attention, causal, tensor-core (mma.sync tf32).
// CTA = 128 threads (4 warps), q-tile 64 rows, warp owns 16 rows.
// Softmax fully warp-local; P converted C-frag -> A-frag via shuffles.
// ===========================================================================
__global__ __launch_bounds__(128) void attn_tc_kernel(void)
{
    __shared__ float Ks[64][68];   // also Q staging; lane addr ≡ 4g+t
    __shared__ float Vs[64][72];   // lane addr ≡ 8t+g

    const int qt = 31 - blockIdx.x;     // big tiles first
    const int h  = blockIdx.y;
    const int b  = blockIdx.z;
    const int tid = threadIdx.x;
    const int wid = tid >> 5, lane = tid & 31;
    const int g = lane >> 2, t = lane & 3;
    const int wrow = wid * 16;

    const float* qbase = g_qkv + (size_t)b * TT * C3 + h * HSZ;
    const float* kbase = qbase + CC;
    const float* vbase = qbase + 2 * CC;

    // stage Q (scaled, tf32) into Ks, then preload A-fragments
    #pragma unroll
    for (int i = 0; i < 8; i++) {
        int idx = tid + i * 128;
        int row = idx >> 4, d4 = idx & 15;
        float4 v = *(const float4*)(qbase + (size_t)(qt*64 + row) * C3 + d4*4);
        float4 c4;
        c4.x = tf32f(v.x * 0.125f); c4.y = tf32f(v.y * 0.125f);
        c4.z = tf32f(v.z * 0.125f); c4.w = tf32f(v.w * 0.125f);
        *(float4*)&Ks[row][d4*4] = c4;
    }
    __syncthreads();
    uint32_t qa[8][4];
    #pragma unroll
    for (int s = 0; s < 8; s++) {
        qa[s][0] = __float_as_uint(Ks[wrow + g    ][s*8 + t    ]);
        qa[s][1] = __float_as_uint(Ks[wrow + g + 8][s*8 + t    ]);
        qa[s][2] = __float_as_uint(Ks[wrow + g    ][s*8 + t + 4]);
        qa[s][3] = __float_as_uint(Ks[wrow + g + 8][s*8 + t + 4]);
    }

    float m_lo = -1e30f, m_hi = -1e30f, l_lo = 0.f, l_hi = 0.f;
    float oa[8][4];
    #pragma unroll
    for (int nb = 0; nb < 8; nb++)
        #pragma unroll
        for (int j = 0; j < 4; j++) oa[nb][j] = 0.f;

    for (int kt = 0; kt <= qt; kt++) {
        __syncthreads();   // frag readers (or Q preload) done with Ks/Vs
        #pragma unroll
        for (int i = 0; i < 8; i++) {
            int idx = tid + i * 128;
            int row = idx >> 4, d4 = idx & 15;
            float4 kv = *(const float4*)(kbase + (size_t)(kt*64 + row) * C3 + d4*4);
            float4 ck;
            ck.x = tf32f(kv.x); ck.y = tf32f(kv.y); ck.z = tf32f(kv.z); ck.w = tf32f(kv.w);
            *(float4*)&Ks[row][d4*4] = ck;
            float4 vv = *(const float4*)(vbase + (size_t)(kt*64 + row) * C3 + d4*4);
            float4 cv;
            cv.x = tf32f(vv.x); cv.y = tf32f(vv.y); cv.z = tf32f(vv.z); cv.w = tf32f(vv.w);
            *(float4*)&Vs[row][d4*4] = cv;
        }
        __syncthreads();

        // S = Q K^T
        float sa[8][4];
        #pragma unroll
        for (int nb = 0; nb < 8; nb++)
            #pragma unroll
            for (int j = 0; j < 4; j++) sa[nb][j] = 0.f;
        #pragma unroll
        for (int s = 0; s < 8; s++) {
            #pragma unroll
            for (int nb = 0; nb < 8; nb++) {
                uint32_t b0 = __float_as_uint(Ks[nb*8 + g][s*8 + t    ]);
                uint32_t b1 = __float_as_uint(Ks[nb*8 + g][s*8 + t + 4]);
                mma_tf32(sa[nb], qa[s], b0, b1);
            }
        }

        // causal mask on diagonal tile
        if (kt == qt) {
            const int rlo = wrow + g, rhi = rlo + 8;
            #pragma unroll
            for (int nb = 0; nb < 8; nb++) {
                int c0 = nb*8 + 2*t, c1 = c0 + 1;
                if (c0 > rlo) sa[nb][0] = -1e30f;
                if (c1 > rlo) sa[nb][1] = -1e30f;
                if (c0 > rhi) sa[nb][2] = -1e30f;
                if (c1 > rhi) sa[nb][3] = -1e30f;
            }
        }

        // online softmax (warp-local; rows live in 4-lane groups -> xor 1,2)
        float mx_lo = -1e30f, mx_hi = -1e30f;
        #pragma unroll
        for (int nb = 0; nb < 8; nb++) {
            mx_lo = fmaxf(mx_lo, fmaxf(sa[nb][0], sa[nb][1]));
            mx_hi = fmaxf(mx_hi, fmaxf(sa[nb][2], sa[nb][3]));
        }
        mx_lo = fmaxf(mx_lo, __shfl_xor_sync(0xffffffffu, mx_lo, 1));
        mx_lo = fmaxf(mx_lo, __shfl_xor_sync(0xffffffffu, mx_lo, 2));
        mx_hi = fmaxf(mx_hi, __shfl_xor_sync(0xffffffffu, mx_hi, 1));
        mx_hi = fmaxf(mx_hi, __shfl_xor_sync(0xffffffffu, mx_hi, 2));

        float mn_lo = fmaxf(m_lo, mx_lo), mn_hi = fmaxf(m_hi, mx_hi);
        float al_lo = __expf(m_lo - mn_lo), al_hi = __expf(m_hi - mn_hi);
        m_lo = mn_lo; m_hi = mn_hi;

        float su_lo = 0.f, su_hi = 0.f;
        #pragma unroll
        for (int nb = 0; nb < 8; nb++) {
            sa[nb][0] = __expf(sa[nb][0] - m_lo); su_lo += sa[nb][0];
            sa[nb][1] = __expf(sa[nb][1] - m_lo); su_lo += sa[nb][1];
            sa[nb][2] = __expf(sa[nb][2] - m_hi); su_hi += sa[nb][2];
            sa[nb][3] = __expf(sa[nb][3] - m_hi); su_hi += sa[nb][3];
        }
        su_lo += __shfl_xor_sync(0xffffffffu, su_lo, 1);
        su_lo += __shfl_xor_sync(0xffffffffu, su_lo, 2);
        su_hi += __shfl_xor_sync(0xffffffffu, su_hi, 1);
        su_hi += __shfl_xor_sync(0xffffffffu, su_hi, 2);
        l_lo = al_lo * l_lo + su_lo;
        l_hi = al_hi * l_hi + su_hi;

        #pragma unroll
        for (int nb = 0; nb < 8; nb++) {
            oa[nb][0] *= al_lo; oa[nb][1] *= al_lo;
            oa[nb][2] *= al_hi; oa[nb][3] *= al_hi;
        }

        // O += P @ V  (P: C-frag -> A-frag via shuffles, cvt to tf32)
        const int src0 = (lane & ~3) | (t >> 1);
        const int src1 = src0 + 2;
        const bool odd = (t & 1);
        #pragma unroll
        for (int s = 0; s < 8; s++) {
            float x0 = __shfl_sync(0xffffffffu, sa[s][0], src0);
            float x1 = __shfl_sync(0xffffffffu, sa[s][1], src0);
            float y0 = __shfl_sync(0xffffffffu, sa[s][0], src1);
            float y1 = __shfl_sync(0xffffffffu, sa[s][1], src1);
            float z0 = __shfl_sync(0xffffffffu, sa[s][2], src0);
            float z1 = __shfl_sync(0xffffffffu, sa[s][3], src0);
            float w0 = __shfl_sync(0xffffffffu, sa[s][2], src1);
            float w1 = __shfl_sync(0xffffffffu, sa[s][3], src1);
            uint32_t pa[4];
            pa[0] = tf32u(odd ? x1 : x0);
            pa[1] = tf32u(odd ? z1 : z0);
            pa[2] = tf32u(odd ? y1 : y0);
            pa[3] = tf32u(odd ? w1 : w0);
            // wait: pa[1]/pa[3] built from sa[2]/sa[3] pairs
            #pragma unroll
            for (int nb = 0; nb < 8; nb++) {
                uint32_t b0 = __float_as_uint(Vs[s*8 + t    ][nb*8 + g]);
                uint32_t b1 = __float_as_uint(Vs[s*8 + t + 4][nb*8 + g]);
                mma_tf32(oa[nb], pa, b0, b1);
            }
        }
    }

    // epilogue: normalize, store
    const float inv_lo = 1.f / l_lo, inv_hi = 1.f / l_hi;
    const int rlo = qt*64 + wrow + g, rhi = rlo + 8;
    #pragma unroll
    for (int nb = 0; nb < 8; nb++) {
        const int col = h * HSZ + nb*8 + 2*t;
        float2 o0 = { oa[nb][0] * inv_lo, oa[nb][1] * inv_lo };
        *(float2*)(g_y + (size_t)(b*TT + rlo) * CC + col) = o0;
        float2 o1 = { oa[nb][2] * inv_hi, oa[nb][3] * inv_hi };
        *(float2*)(g_y + (size_t)(b*TT + rhi) * CC + col) = o1;
    }
}

// ---------------------------------------------------------------------------
extern "C" void kernel_launch(void* const* d_in, const int* in_sizes, int n_in,
                              void* d_out, int out_size)
{
    const float* x      = (const float*)d_in[0];
    const float* w_attn = (const float*)d_in[1];
    const float* b_attn = (const float*)d_in[2];
    const float* w_proj = (const float*)d_in[3];
    const float* b_proj = (const float*)d_in[4];
    float* out = (float*)d_out;

    float* qkv; float* y;
    cudaGetSymbolAddress((void**)&qkv, g_qkv);
    cudaGetSymbolAddress((void**)&y,   g_y);

    const int gsmem = GSMEM_FLOATS * sizeof(float);   // 71680
    static bool attr_done = false;
    if (!attr_done) {
        cudaFuncSetAttribute(gemm_tc_kernel,
                             cudaFuncAttributeMaxDynamicSharedMemorySize, gsmem);
        attr_done = true;
    }

    // 1) qkv = x @ w_attn + b_attn   [8192, 2304]
    {
        dim3 grid(C3 / 128, MTOT / 128);
        gemm_tc_kernel<<<grid, 256, gsmem>>>(x, w_attn, b_attn, qkv, MTOT, C3, CC);
    }
    // 2) flash attention -> g_y [8192, 768]
    {
        dim3 grid(TT / 64, NH, BB);
        attn_tc_kernel<<<grid, 128>>>();
    }
    // 3) out = y @ w_proj + b_proj   [8192, 768]
    {
        dim3 grid(CC / 128, MTOT / 128);
        gemm_tc_kernel<<<grid, 256, gsmem>>>(y, w_proj, b_proj, out, MTOT, CC, CC);
    }
}

// round 6
// speedup vs baseline: 4.2554x; 1.2000x over previous
#include <cuda_runtime.h>
#include <cstdint>
#include <math.h>

// Problem constants
#define BB   4
#define TT   2048
#define CC   768
#define NH   12
#define HSZ  64
#define C3   (3*CC)
#define MTOT (BB*TT)      // 8192

// Scratch (allocation-free: __device__ globals)
__device__ float g_qkv[(size_t)MTOT * C3];   // [B*T, 3C] (tf32-rounded values)
__device__ float g_y[(size_t)MTOT * CC];     // [B*T, C]  (tf32-rounded values)
__device__ float g_xr[(size_t)MTOT * CC];    // tf32(x)
__device__ float g_war[(size_t)CC * C3];     // tf32(w_attn)
__device__ float g_wpr[(size_t)CC * CC];     // tf32(w_proj)

// ---------------------------------------------------------------------------
// helpers
// ---------------------------------------------------------------------------
__device__ __forceinline__ uint32_t smem_u32(const void* p) {
    uint32_t a;
    asm("{ .reg .u64 t; cvta.to.shared.u64 t, %1; cvt.u32.u64 %0, t; }" : "=r"(a) : "l"(p));
    return a;
}
__device__ __forceinline__ float tf32f(float x) {
    uint32_t u;
    asm("cvt.rna.tf32.f32 %0, %1;" : "=r"(u) : "f"(x));
    return __uint_as_float(u);
}
__device__ __forceinline__ uint32_t tf32u(float x) {
    uint32_t u;
    asm("cvt.rna.tf32.f32 %0, %1;" : "=r"(u) : "f"(x));
    return u;
}
__device__ __forceinline__ void mma_tf32(float c[4], const uint32_t a[4],
                                         uint32_t b0, uint32_t b1) {
    asm volatile(
        "mma.sync.aligned.m16n8k8.row.col.f32.tf32.tf32.f32 "
        "{%0,%1,%2,%3}, {%4,%5,%6,%7}, {%8,%9}, {%0,%1,%2,%3};"
        : "+f"(c[0]), "+f"(c[1]), "+f"(c[2]), "+f"(c[3])
        : "r"(a[0]), "r"(a[1]), "r"(a[2]), "r"(a[3]), "r"(b0), "r"(b1));
}
__device__ __forceinline__ void cpasync16(uint32_t dst, const void* src) {
    asm volatile("cp.async.cg.shared.global [%0], [%1], 16;" :: "r"(dst), "l"(src));
}
#define CP_COMMIT() asm volatile("cp.async.commit_group;" ::: "memory")
#define CP_WAIT(n_) asm volatile("cp.async.wait_group %0;" :: "n"(n_) : "memory")

// ---------------------------------------------------------------------------
// pre-pass: tf32-round an array (n % 4 == 0)
// ---------------------------------------------------------------------------
__global__ __launch_bounds__(256) void round_tf32_kernel(
    const float* __restrict__ src, float* __restrict__ dst, int n4)
{
    int i = blockIdx.x * 256 + threadIdx.x;
    if (i < n4) {
        float4 v = ((const float4*)src)[i];
        float4 o;
        o.x = tf32f(v.x); o.y = tf32f(v.y); o.z = tf32f(v.z); o.w = tf32f(v.w);
        ((float4*)dst)[i] = o;
    }
}

// ===========================================================================
// Tensor-core GEMM v2: C = A@B + bias. Inputs already tf32-rounded in gmem.
// CTA 128x128, BK=32, 8 warps (2x4), 3-stage cp.async pipeline.
// ===========================================================================
#define GA_PITCH 36
#define GB_PITCH 136
#define GSTG (128*GA_PITCH + 32*GB_PITCH)        // floats per stage = 8960
#define GSTAGES 3
#define GSMEM_BYTES (GSTAGES * GSTG * 4)         // 107520

template<bool ROUND_OUT>
__global__ __launch_bounds__(256, 2) void gemm_tc2_kernel(
    const float* __restrict__ A, const float* __restrict__ B,
    const float* __restrict__ bias, float* __restrict__ C,
    int M, int N, int K)
{
    extern __shared__ float sm[];
    const uint32_t sbase = smem_u32(sm);
    const int tid = threadIdx.x;
    const int wid = tid >> 5, lane = tid & 31;
    const int g = lane >> 2, t = lane & 3;
    const int wm = wid >> 2, wn = wid & 3;
    const int m0 = blockIdx.y * 128, n0 = blockIdx.x * 128;

    const int arow = tid >> 3, ak4 = tid & 7;     // A loader: +256 -> +32 rows
    const int brow = tid >> 5, bn4 = tid & 31;    // B loader: +256 -> +8 rows

    auto issue = [&](int s, int k0) {
        const uint32_t sa = sbase + (uint32_t)(s * GSTG) * 4u;
        const uint32_t sb = sa + 128u * GA_PITCH * 4u;
        #pragma unroll
        for (int r = 0; r < 4; r++)
            cpasync16(sa + ((arow + r*32) * GA_PITCH + ak4*4) * 4u,
                      A + (size_t)(m0 + arow + r*32) * K + k0 + ak4*4);
        #pragma unroll
        for (int r = 0; r < 4; r++)
            cpasync16(sb + ((brow + r*8) * GB_PITCH + bn4*4) * 4u,
                      B + (size_t)(k0 + brow + r*8) * N + n0 + bn4*4);
    };

    float acc[4][4][4];
    #pragma unroll
    for (int mt = 0; mt < 4; mt++)
        #pragma unroll
        for (int nt = 0; nt < 4; nt++)
            #pragma unroll
            for (int j = 0; j < 4; j++) acc[mt][nt][j] = 0.f;

    const int nk = K >> 5;
    #pragma unroll
    for (int s = 0; s < GSTAGES - 1; s++) { issue(s, s << 5); CP_COMMIT(); }

    for (int i = 0; i < nk; i++) {
        CP_WAIT(GSTAGES - 2);
        __syncthreads();
        if (i + GSTAGES - 1 < nk) issue((i + GSTAGES - 1) % GSTAGES,
                                        (i + GSTAGES - 1) << 5);
        CP_COMMIT();

        const float* As_ = sm + (i % GSTAGES) * GSTG;
        const float* Bs_ = As_ + 128 * GA_PITCH;
        #pragma unroll
        for (int ks = 0; ks < 4; ks++) {
            uint32_t af[4][4];
            #pragma unroll
            for (int mt = 0; mt < 4; mt++) {
                const int row = wm*64 + mt*16;
                af[mt][0] = __float_as_uint(As_[(row + g    ) * GA_PITCH + ks*8 + t    ]);
                af[mt][1] = __float_as_uint(As_[(row + g + 8) * GA_PITCH + ks*8 + t    ]);
                af[mt][2] = __float_as_uint(As_[(row + g    ) * GA_PITCH + ks*8 + t + 4]);
                af[mt][3] = __float_as_uint(As_[(row + g + 8) * GA_PITCH + ks*8 + t + 4]);
            }
            #pragma unroll
            for (int nt = 0; nt < 4; nt++) {
                uint32_t b0 = __float_as_uint(Bs_[(ks*8 + t    ) * GB_PITCH + wn*32 + nt*8 + g]);
                uint32_t b1 = __float_as_uint(Bs_[(ks*8 + t + 4) * GB_PITCH + wn*32 + nt*8 + g]);
                #pragma unroll
                for (int mt = 0; mt < 4; mt++)
                    mma_tf32(acc[mt][nt], af[mt], b0, b1);
            }
        }
    }

    // epilogue
    float2 bv[4];
    #pragma unroll
    for (int nt = 0; nt < 4; nt++)
        bv[nt] = *(const float2*)(bias + n0 + wn*32 + nt*8 + 2*t);
    #pragma unroll
    for (int mt = 0; mt < 4; mt++) {
        const int row = m0 + wm*64 + mt*16 + g;
        #pragma unroll
        for (int nt = 0; nt < 4; nt++) {
            const int col = n0 + wn*32 + nt*8 + 2*t;
            float2 o0 = { acc[mt][nt][0] + bv[nt].x, acc[mt][nt][1] + bv[nt].y };
            float2 o1 = { acc[mt][nt][2] + bv[nt].x, acc[mt][nt][3] + bv[nt].y };
            if (ROUND_OUT) {
                o0.x = tf32f(o0.x); o0.y = tf32f(o0.y);
                o1.x = tf32f(o1.x); o1.y = tf32f(o1.y);
            }
            *(float2*)(C + (size_t)row * N + col) = o0;
            *(float2*)(C + (size_t)(row + 8) * N + col) = o1;
        }
    }
}

// ===========================================================================
// Flash attention v2: causal, tensor-core, cp.async double-buffered K/V.
// CTA = 128 threads (4 warps), q-tile 64 rows, warp owns 16 rows.
// All gmem operands already tf32-rounded. One __syncthreads per iteration.
// ===========================================================================
#define AK_PITCH 68
#define AV_PITCH 72
#define A_K(s) ((s) * 64 * AK_PITCH)                       // float offsets
#define A_V(s) (2*64*AK_PITCH + (s) * 64 * AV_PITCH)
#define ASMEM_BYTES ((2*64*AK_PITCH + 2*64*AV_PITCH) * 4)  // 71680

__global__ __launch_bounds__(128, 2) void attn_tc2_kernel(void)
{
    extern __shared__ float sm[];
    const uint32_t sbase = smem_u32(sm);

    const int qt = 31 - blockIdx.x;     // big tiles first
    const int h  = blockIdx.y;
    const int b  = blockIdx.z;
    const int tid = threadIdx.x;
    const int wid = tid >> 5, lane = tid & 31;
    const int g = lane >> 2, t = lane & 3;
    const int wrow = wid * 16;

    const float* qbase = g_qkv + (size_t)b * TT * C3 + h * HSZ;
    const float* kbase = qbase + CC;
    const float* vbase = qbase + 2 * CC;

    auto issueKV = [&](int kt, int s) {
        const uint32_t ka = sbase + A_K(s) * 4u;
        const uint32_t va = sbase + A_V(s) * 4u;
        #pragma unroll
        for (int i = 0; i < 8; i++) {
            int idx = tid + i * 128;
            int row = idx >> 4, c4 = idx & 15;
            cpasync16(ka + (row * AK_PITCH + c4*4) * 4u,
                      kbase + (size_t)(kt*64 + row) * C3 + c4*4);
            cpasync16(va + (row * AV_PITCH + c4*4) * 4u,
                      vbase + (size_t)(kt*64 + row) * C3 + c4*4);
        }
    };

    // stage Q into K-buffer 1 via cp.async (group 0), K/V tile 0 (group 1)
    {
        const uint32_t ka = sbase + A_K(1) * 4u;
        #pragma unroll
        for (int i = 0; i < 8; i++) {
            int idx = tid + i * 128;
            int row = idx >> 4, c4 = idx & 15;
            cpasync16(ka + (row * AK_PITCH + c4*4) * 4u,
                      qbase + (size_t)(qt*64 + row) * C3 + c4*4);
        }
        CP_COMMIT();
    }
    issueKV(0, 0);
    CP_COMMIT();

    CP_WAIT(1);              // Q arrived
    __syncthreads();

    uint32_t qa[8][4];
    {
        const float* Q = sm + A_K(1);
        #pragma unroll
        for (int s = 0; s < 8; s++) {   // fold softmax scale into Q (exact pow2)
            qa[s][0] = __float_as_uint(0.125f * Q[(wrow + g    ) * AK_PITCH + s*8 + t    ]);
            qa[s][1] = __float_as_uint(0.125f * Q[(wrow + g + 8) * AK_PITCH + s*8 + t    ]);
            qa[s][2] = __float_as_uint(0.125f * Q[(wrow + g    ) * AK_PITCH + s*8 + t + 4]);
            qa[s][3] = __float_as_uint(0.125f * Q[(wrow + g + 8) * AK_PITCH + s*8 + t + 4]);
        }
    }

    float m_lo = -1e30f, m_hi = -1e30f, l_lo = 0.f, l_hi = 0.f;
    float oa[8][4];
    #pragma unroll
    for (int nb = 0; nb < 8; nb++)
        #pragma unroll
        for (int j = 0; j < 4; j++) oa[nb][j] = 0.f;

    for (int kt = 0; kt <= qt; kt++) {
        CP_WAIT(0);          // K/V tile kt arrived (this thread's chunks)
        __syncthreads();     // all chunks visible; prev compute done everywhere
        if (kt + 1 <= qt) issueKV(kt + 1, (kt + 1) & 1);
        CP_COMMIT();

        const int s0 = kt & 1;
        const float* Ksm = sm + A_K(s0);
        const float* Vsm = sm + A_V(s0);

        // S = Q K^T
        float sa[8][4];
        #pragma unroll
        for (int nb = 0; nb < 8; nb++)
            #pragma unroll
            for (int j = 0; j < 4; j++) sa[nb][j] = 0.f;
        #pragma unroll
        for (int s = 0; s < 8; s++) {
            #pragma unroll
            for (int nb = 0; nb < 8; nb++) {
                uint32_t b0 = __float_as_uint(Ksm[(nb*8 + g) * AK_PITCH + s*8 + t    ]);
                uint32_t b1 = __float_as_uint(Ksm[(nb*8 + g) * AK_PITCH + s*8 + t + 4]);
                mma_tf32(sa[nb], qa[s], b0, b1);
            }
        }

        // causal mask on diagonal tile
        if (kt == qt) {
            const int rlo = wrow + g, rhi = rlo + 8;
            #pragma unroll
            for (int nb = 0; nb < 8; nb++) {
                int c0 = nb*8 + 2*t, c1 = c0 + 1;
                if (c0 > rlo) sa[nb][0] = -1e30f;
                if (c1 > rlo) sa[nb][1] = -1e30f;
                if (c0 > rhi) sa[nb][2] = -1e30f;
                if (c1 > rhi) sa[nb][3] = -1e30f;
            }
        }

        // online softmax (warp-local)
        float mx_lo = -1e30f, mx_hi = -1e30f;
        #pragma unroll
        for (int nb = 0; nb < 8; nb++) {
            mx_lo = fmaxf(mx_lo, fmaxf(sa[nb][0], sa[nb][1]));
            mx_hi = fmaxf(mx_hi, fmaxf(sa[nb][2], sa[nb][3]));
        }
        mx_lo = fmaxf(mx_lo, __shfl_xor_sync(0xffffffffu, mx_lo, 1));
        mx_lo = fmaxf(mx_lo, __shfl_xor_sync(0xffffffffu, mx_lo, 2));
        mx_hi = fmaxf(mx_hi, __shfl_xor_sync(0xffffffffu, mx_hi, 1));
        mx_hi = fmaxf(mx_hi, __shfl_xor_sync(0xffffffffu, mx_hi, 2));

        float mn_lo = fmaxf(m_lo, mx_lo), mn_hi = fmaxf(m_hi, mx_hi);
        float al_lo = __expf(m_lo - mn_lo), al_hi = __expf(m_hi - mn_hi);
        m_lo = mn_lo; m_hi = mn_hi;

        float su_lo = 0.f, su_hi = 0.f;
        #pragma unroll
        for (int nb = 0; nb < 8; nb++) {
            sa[nb][0] = __expf(sa[nb][0] - m_lo); su_lo += sa[nb][0];
            sa[nb][1] = __expf(sa[nb][1] - m_lo); su_lo += sa[nb][1];
            sa[nb][2] = __expf(sa[nb][2] - m_hi); su_hi += sa[nb][2];
            sa[nb][3] = __expf(sa[nb][3] - m_hi); su_hi += sa[nb][3];
        }
        su_lo += __shfl_xor_sync(0xffffffffu, su_lo, 1);
        su_lo += __shfl_xor_sync(0xffffffffu, su_lo, 2);
        su_hi += __shfl_xor_sync(0xffffffffu, su_hi, 1);
        su_hi += __shfl_xor_sync(0xffffffffu, su_hi, 2);
        l_lo = al_lo * l_lo + su_lo;
        l_hi = al_hi * l_hi + su_hi;

        #pragma unroll
        for (int nb = 0; nb < 8; nb++) {
            oa[nb][0] *= al_lo; oa[nb][1] *= al_lo;
            oa[nb][2] *= al_hi; oa[nb][3] *= al_hi;
        }

        // O += P @ V  (P: C-frag -> A-frag via shuffles)
        const int src0 = (lane & ~3) | (t >> 1);
        const int src1 = src0 + 2;
        const bool odd = (t & 1);
        #pragma unroll
        for (int s = 0; s < 8; s++) {
            float x0 = __shfl_sync(0xffffffffu, sa[s][0], src0);
            float x1 = __shfl_sync(0xffffffffu, sa[s][1], src0);
            float y0 = __shfl_sync(0xffffffffu, sa[s][0], src1);
            float y1 = __shfl_sync(0xffffffffu, sa[s][1], src1);
            float z0 = __shfl_sync(0xffffffffu, sa[s][2], src0);
            float z1 = __shfl_sync(0xffffffffu, sa[s][3], src0);
            float w0 = __shfl_sync(0xffffffffu, sa[s][2], src1);
            float w1 = __shfl_sync(0xffffffffu, sa[s][3], src1);
            uint32_t pa[4];
            pa[0] = tf32u(odd ? x1 : x0);
            pa[1] = tf32u(odd ? z1 : z0);
            pa[2] = tf32u(odd ? y1 : y0);
            pa[3] = tf32u(odd ? w1 : w0);
            #pragma unroll
            for (int nb = 0; nb < 8; nb++) {
                uint32_t b0 = __float_as_uint(Vsm[(s*8 + t    ) * AV_PITCH + nb*8 + g]);
                uint32_t b1 = __float_as_uint(Vsm[(s*8 + t + 4) * AV_PITCH + nb*8 + g]);
                mma_tf32(oa[nb], pa, b0, b1);
            }
        }
    }

    // epilogue: normalize, round to tf32 (proj GEMM consumes raw), store
    const float inv_lo = 1.f / l_lo, inv_hi = 1.f / l_hi;
    const int rlo = qt*64 + wrow + g, rhi = rlo + 8;
    #pragma unroll
    for (int nb = 0; nb < 8; nb++) {
        const int col = h * HSZ + nb*8 + 2*t;
        float2 o0 = { tf32f(oa[nb][0] * inv_lo), tf32f(oa[nb][1] * inv_lo) };
        *(float2*)(g_y + (size_t)(b*TT + rlo) * CC + col) = o0;
        float2 o1 = { tf32f(oa[nb][2] * inv_hi), tf32f(oa[nb][3] * inv_hi) };
        *(float2*)(g_y + (size_t)(b*TT + rhi) * CC + col) = o1;
    }
}

// ---------------------------------------------------------------------------
extern "C" void kernel_launch(void* const* d_in, const int* in_sizes, int n_in,
                              void* d_out, int out_size)
{
    const float* x      = (const float*)d_in[0];
    const float* w_attn = (const float*)d_in[1];
    const float* b_attn = (const float*)d_in[2];
    const float* w_proj = (const float*)d_in[3];
    const float* b_proj = (const float*)d_in[4];
    float* out = (float*)d_out;

    float *qkv, *y, *xr, *war, *wpr;
    cudaGetSymbolAddress((void**)&qkv, g_qkv);
    cudaGetSymbolAddress((void**)&y,   g_y);
    cudaGetSymbolAddress((void**)&xr,  g_xr);
    cudaGetSymbolAddress((void**)&war, g_war);
    cudaGetSymbolAddress((void**)&wpr, g_wpr);

    static bool attr_done = false;
    if (!attr_done) {
        cudaFuncSetAttribute(gemm_tc2_kernel<true>,
                             cudaFuncAttributeMaxDynamicSharedMemorySize, GSMEM_BYTES);
        cudaFuncSetAttribute(gemm_tc2_kernel<false>,
                             cudaFuncAttributeMaxDynamicSharedMemorySize, GSMEM_BYTES);
        cudaFuncSetAttribute(attn_tc2_kernel,
                             cudaFuncAttributeMaxDynamicSharedMemorySize, ASMEM_BYTES);
        attr_done = true;
    }

    // 0) tf32-round inputs (memory-bound pre-pass)
    {
        int n4;
        n4 = (MTOT * CC) / 4;
        round_tf32_kernel<<<(n4 + 255) / 256, 256>>>(x, xr, n4);
        n4 = (CC * C3) / 4;
        round_tf32_kernel<<<(n4 + 255) / 256, 256>>>(w_attn, war, n4);
        n4 = (CC * CC) / 4;
        round_tf32_kernel<<<(n4 + 255) / 256, 256>>>(w_proj, wpr, n4);
    }
    // 1) qkv = xr @ war + b_attn (stores tf32-rounded)
    {
        dim3 grid(C3 / 128, MTOT / 128);
        gemm_tc2_kernel<true><<<grid, 256, GSMEM_BYTES>>>(xr, war, b_attn, qkv, MTOT, C3, CC);
    }
    // 2) flash attention -> g_y (stores tf32-rounded)
    {
        dim3 grid(TT / 64, NH, BB);
        attn_tc2_kernel<<<grid, 128, ASMEM_BYTES>>>();
    }
    // 3) out = y @ wpr + b_proj (full-precision store)
    {
        dim3 grid(CC / 128, MTOT / 128);
        gemm_tc2_kernel<false><<<grid, 256, GSMEM_BYTES>>>(y, wpr, b_proj, out, MTOT, CC, CC);
    }
}